// round 6
// baseline (speedup 1.0000x reference)
#include <cuda_runtime.h>
#include <cuda_bf16.h>
#include <cstdint>

#define DIM   1024
#define NQ    10
#define NWIN  65472
#define NWPB  4092
#define NPAD  65536

typedef unsigned long long ull;
typedef unsigned int uint;

// M = R*E split to bf16 hi/lo, layout [d][j]
__device__ __nv_bfloat16 g_Bh[DIM * DIM];
__device__ __nv_bfloat16 g_Bl[DIM * DIM];
// s-state split to bf16 hi/lo, layout [n][j], padded to NPAD rows (zeros past NWIN)
__device__ __nv_bfloat16 g_Ah[(size_t)NPAD * DIM];
__device__ __nv_bfloat16 g_Al[(size_t)NPAD * DIM];

static __device__ __forceinline__ uint smem_u32(const void* p) {
    return (uint)__cvta_generic_to_shared(p);
}
__device__ __forceinline__ void cpasync16(uint dst, const void* src) {
    asm volatile("cp.async.cg.shared.global [%0], [%1], 16;" :: "r"(dst), "l"(src) : "memory");
}
#define CP_COMMIT asm volatile("cp.async.commit_group;" ::: "memory")
#define CP_WAIT1  asm volatile("cp.async.wait_group 1;" ::: "memory")
#define CP_WAIT0  asm volatile("cp.async.wait_group 0;" ::: "memory")

__device__ __forceinline__ void ldsm4(uint* r, uint addr) {
    asm volatile("ldmatrix.sync.aligned.m8n8.x4.shared.b16 {%0,%1,%2,%3}, [%4];"
                 : "=r"(r[0]), "=r"(r[1]), "=r"(r[2]), "=r"(r[3]) : "r"(addr));
}
__device__ __forceinline__ void mma16816(float* c, const uint* a, const uint* b) {
    asm volatile("mma.sync.aligned.m16n8k16.row.col.f32.bf16.bf16.f32 "
        "{%0,%1,%2,%3},{%4,%5,%6,%7},{%8,%9},{%0,%1,%2,%3};"
        : "+f"(c[0]), "+f"(c[1]), "+f"(c[2]), "+f"(c[3])
        : "r"(a[0]), "r"(a[1]), "r"(a[2]), "r"(a[3]), "r"(b[0]), "r"(b[1]));
}

// ---------------------------------------------------------------------------
// Kernel 1: M = R*E, split to bf16 hi/lo in [d][j] layout.
// ---------------------------------------------------------------------------
__global__ __launch_bounds__(256) void rot_kernel(const float* __restrict__ E,
                                                  const float* __restrict__ theta) {
    __shared__ float sm[8 * 1028];
    const int tid = threadIdx.x;
    const int j0 = blockIdx.x * 8;

    float ct[NQ], st[NQ];
#pragma unroll
    for (int i = 0; i < NQ; i++) sincosf(0.5f * theta[i], &st[i], &ct[i]);

    for (int idx = tid; idx < 8192; idx += 256) {
        int c = idx & 7, d = idx >> 3;
        sm[c * 1028 + d] = E[d * DIM + j0 + c];
    }
    __syncthreads();

    for (int i = 0; i < NQ; i++) {
        const int m = 9 - i;
        for (int t = tid; t < 4096; t += 256) {
            int c = t >> 9, p = t & 511;
            int low = p & ((1 << m) - 1);
            int d0 = ((p >> m) << (m + 1)) | low;
            int d1 = d0 | (1 << m);
            float a0 = sm[c * 1028 + d0];
            float a1 = sm[c * 1028 + d1];
            sm[c * 1028 + d0] = ct[i] * a0 - st[i] * a1;
            sm[c * 1028 + d1] = st[i] * a0 + ct[i] * a1;
        }
        __syncthreads();
    }

    for (int idx = tid; idx < 8192; idx += 256) {
        int c = idx & 7, d = idx >> 3;
        float m = sm[c * 1028 + d];
        __nv_bfloat16 h = __float2bfloat16(m);
        float lo = m - __bfloat162float(h);
        g_Bh[d * DIM + j0 + c] = h;
        g_Bl[d * DIM + j0 + c] = __float2bfloat16(lo);
    }
}

// ---------------------------------------------------------------------------
// Kernel 2: build A = s-state (bf16 hi/lo). One warp per window.
// ---------------------------------------------------------------------------
__global__ __launch_bounds__(128) void state_kernel(const float* __restrict__ x) {
    const int tid = threadIdx.x, lane = tid & 31;
    const int n = blockIdx.x * 4 + (tid >> 5);
    float phi_u = 0.0f, plo_u = 0.0f;
    if (n < NWIN) {
        const int b = n / NWPB;
        const int pos = n - b * NWPB;
        float cs[2][5], sn[2][5];
#pragma unroll
        for (int c = 0; c < 2; c++)
#pragma unroll
            for (int k = 0; k < 5; k++) {
                float v = x[((b * 2 + c) << 12) + pos + k];
                sincosf(0.5f * v, &sn[c][k], &cs[c][k]);
            }
        phi_u = 1.0f; plo_u = 1.0f;
#pragma unroll
        for (int i = 0; i < 5; i++) {
            int bit = (lane >> (4 - i)) & 1;
            phi_u *= bit ? sn[0][i] : cs[0][i];
            plo_u *= bit ? sn[1][i] : cs[1][i];
        }
    }
    __nv_bfloat16* Ah = g_Ah + (size_t)n * DIM;
    __nv_bfloat16* Al = g_Al + (size_t)n * DIM;
#pragma unroll 4
    for (int rep = 0; rep < 32; rep++) {
        float ph = __shfl_sync(0xffffffffu, phi_u, rep);
        float s = ph * plo_u;
        __nv_bfloat16 h = __float2bfloat16(s);
        float lo = s - __bfloat162float(h);
        Ah[rep * 32 + lane] = h;
        Al[rep * 32 + lane] = __float2bfloat16(lo);
    }
}

// ---------------------------------------------------------------------------
// Kernel 3: bf16-split GEMM via mma.sync + signed-square epilogue.
// Block = 128 windows x 1024 d (8 N=128 chunks). Kc=32 stages, 3-ring.
// Stage (32KB): A[128 rows][Ah 64B | Al 64B], B[128 rows][Bh 64B | Bl 64B],
// 16B-chunk XOR-(row&7) swizzle on the 128B row. 2 CTAs/SM.
// ---------------------------------------------------------------------------
#define STG 32768
#define ZSM_OFF (3 * STG)
#define SMEM_BYTES (3 * STG + 512)

__device__ __forceinline__ void load_stage(uint sb, int s, int n0, int tid) {
    const int buf = s % 3;
    const int kc = s & 31, dc = s >> 5;
    const int row = tid >> 1;
    const int half = tid & 1;             // 0 -> hi chunks 0..3, 1 -> lo chunks 4..7
    const int r7 = row & 7;
    const uint dbase = sb + (uint)buf * STG + (uint)row * 128;
    const char* aSrc = (const char*)((half ? g_Al : g_Ah) + (size_t)(n0 + row) * DIM + kc * 32);
    const char* bSrc = (const char*)((half ? g_Bl : g_Bh) + (size_t)(dc * 128 + row) * DIM + kc * 32);
#pragma unroll
    for (int cc = 0; cc < 4; cc++) {
        int c = half * 4 + cc;
        uint sw = (uint)((c ^ r7) << 4);
        cpasync16(dbase + sw,         aSrc + cc * 16);
        cpasync16(dbase + 16384 + sw, bSrc + cc * 16);
    }
    CP_COMMIT;
}

__global__ __launch_bounds__(256, 2) void qmma_kernel(float* __restrict__ out) {
    extern __shared__ __align__(128) char smem[];
    const uint sb = smem_u32(smem);
    const int tid = threadIdx.x, lane = tid & 31, wid = tid >> 5;
    const int warp_m = wid & 3, warp_n = wid >> 2;
    const int n0 = blockIdx.x * 128;
    float* zsm = (float*)(smem + ZSM_OFF);
    if (tid < 128) zsm[tid] = 0.0f;

    // ldmatrix addressing constants
    const int arow0 = warp_m * 32 + (lane & 15);     // + 16*i per m-tile
    const int ahi = lane >> 4;                        // 16B k-half select
    int nrow[4];
#pragma unroll
    for (int jj = 0; jj < 4; jj++)
        nrow[jj] = warp_n * 64 + jj * 16 + ((lane >> 4) & 1) * 8 + (lane & 7);
    const int bhi = (lane >> 3) & 1;

    float acc[64];
#pragma unroll
    for (int i = 0; i < 64; i++) acc[i] = 0.0f;

    load_stage(sb, 0, n0, tid);
    load_stage(sb, 1, n0, tid);

    for (int s = 0; s < 256; s++) {
        if (s < 254) CP_WAIT1; else CP_WAIT0;
        __syncthreads();
        if (s + 2 < 256) load_stage(sb, s + 2, n0, tid);

        const uint abase = sb + (uint)(s % 3) * STG;
        const uint bbase = abase + 16384;
#pragma unroll
        for (int ks = 0; ks < 2; ks++) {
            uint ah[8], al[8];
#pragma unroll
            for (int i = 0; i < 2; i++) {
                int row = arow0 + 16 * i;
                uint base = abase + (uint)row * 128;
                ldsm4(&ah[i * 4], base + (uint)(((ks * 2 + ahi) ^ (row & 7)) << 4));
                ldsm4(&al[i * 4], base + (uint)(((4 + ks * 2 + ahi) ^ (row & 7)) << 4));
            }
#pragma unroll
            for (int jj = 0; jj < 4; jj++) {
                uint bh[4], bl[4];
                uint base = bbase + (uint)nrow[jj] * 128;
                ldsm4(bh, base + (uint)(((ks * 2 + bhi) ^ (nrow[jj] & 7)) << 4));
                ldsm4(bl, base + (uint)(((4 + ks * 2 + bhi) ^ (nrow[jj] & 7)) << 4));
#pragma unroll
                for (int i = 0; i < 2; i++)
#pragma unroll
                    for (int jh = 0; jh < 2; jh++) {
                        float* c = &acc[(i * 8 + jj * 2 + jh) * 4];
                        mma16816(c, &ah[i * 4], &bh[jh * 2]);
                        mma16816(c, &ah[i * 4], &bl[jh * 2]);
                        mma16816(c, &al[i * 4], &bh[jh * 2]);
                    }
            }
        }

        if ((s & 31) == 31) {                        // end of d-chunk
            const float sgn = ((s >> 5) < 4) ? 1.0f : -1.0f;
#pragma unroll
            for (int i = 0; i < 2; i++) {
                float r0 = 0.0f, r1 = 0.0f;
#pragma unroll
                for (int j = 0; j < 8; j++) {
                    float* c = &acc[(i * 8 + j) * 4];
                    r0 = fmaf(c[0], c[0], fmaf(c[1], c[1], r0));
                    r1 = fmaf(c[2], c[2], fmaf(c[3], c[3], r1));
                }
                r0 += __shfl_xor_sync(0xffffffffu, r0, 1);
                r0 += __shfl_xor_sync(0xffffffffu, r0, 2);
                r1 += __shfl_xor_sync(0xffffffffu, r1, 1);
                r1 += __shfl_xor_sync(0xffffffffu, r1, 2);
                if ((lane & 3) == 0) {
                    int mrow = warp_m * 32 + i * 16 + (lane >> 2);
                    atomicAdd(&zsm[mrow],     sgn * r0);
                    atomicAdd(&zsm[mrow + 8], sgn * r1);
                }
            }
#pragma unroll
            for (int i = 0; i < 64; i++) acc[i] = 0.0f;
        }
    }

    __syncthreads();
    if (tid < 128) {
        int n = n0 + tid;
        if (n < NWIN) out[n] = zsm[tid];
    }
}

// ---------------------------------------------------------------------------
extern "C" void kernel_launch(void* const* d_in, const int* in_sizes, int n_in,
                              void* d_out, int out_size) {
    const float* x     = (const float*)d_in[0];
    const float* E     = (const float*)d_in[1];
    const float* theta = (const float*)d_in[2];
    float* out = (float*)d_out;

    rot_kernel<<<DIM / 8, 256>>>(E, theta);
    state_kernel<<<NPAD / 4, 128>>>(x);

    cudaFuncSetAttribute(qmma_kernel,
                         cudaFuncAttributeMaxDynamicSharedMemorySize, SMEM_BYTES);
    qmma_kernel<<<NPAD / 128, 256, SMEM_BYTES>>>(out);
}

// round 7
// speedup vs baseline: 1.6312x; 1.6312x over previous
#include <cuda_runtime.h>
#include <cuda_bf16.h>
#include <cstdint>

#define DIM   1024
#define NQ    10
#define NWIN  65472
#define NWPB  4092
#define NPAD  65536
#define NTILES  36
#define NSTAGES 72

typedef unsigned long long ull;
typedef unsigned int uint;

// M^T hi/lo [j][d], and sign-folded M^T (sgn_d applied) for Q = M^T Sigma M
__device__ __nv_bfloat16 g_Mth[DIM * DIM];
__device__ __nv_bfloat16 g_Mtl[DIM * DIM];
__device__ __nv_bfloat16 g_Msh[DIM * DIM];
__device__ __nv_bfloat16 g_Msl[DIM * DIM];
// Q (lower-triangular tiles, off-diag pre-scaled x2), bf16 hi/lo, [j][j']
__device__ __nv_bfloat16 g_Qh[DIM * DIM];
__device__ __nv_bfloat16 g_Ql[DIM * DIM];
// s-state split bf16 hi/lo [n][j] (zeros past NWIN), plus fp32 copy for weights
__device__ __nv_bfloat16 g_Ah[(size_t)NPAD * DIM];
__device__ __nv_bfloat16 g_Al[(size_t)NPAD * DIM];
__device__ float         g_Sf[(size_t)NPAD * DIM];

// tile (r,c) tables for the 36 lower-triangular tiles
__device__ const unsigned char RT[NTILES] =
    {0,1,1,2,2,2,3,3,3,3,4,4,4,4,4,5,5,5,5,5,5,6,6,6,6,6,6,6,7,7,7,7,7,7,7,7};
__device__ const unsigned char CT[NTILES] =
    {0,0,1,0,1,2,0,1,2,3,0,1,2,3,4,0,1,2,3,4,5,0,1,2,3,4,5,6,0,1,2,3,4,5,6,7};

static __device__ __forceinline__ uint smem_u32(const void* p) {
    return (uint)__cvta_generic_to_shared(p);
}
__device__ __forceinline__ void cpasync16(uint dst, const void* src) {
    asm volatile("cp.async.cg.shared.global [%0], [%1], 16;" :: "r"(dst), "l"(src) : "memory");
}
#define CP_COMMIT asm volatile("cp.async.commit_group;" ::: "memory")
#define CP_WAIT1  asm volatile("cp.async.wait_group 1;" ::: "memory")
#define CP_WAIT0  asm volatile("cp.async.wait_group 0;" ::: "memory")

__device__ __forceinline__ void ldsm4(uint* r, uint addr) {
    asm volatile("ldmatrix.sync.aligned.m8n8.x4.shared.b16 {%0,%1,%2,%3}, [%4];"
                 : "=r"(r[0]), "=r"(r[1]), "=r"(r[2]), "=r"(r[3]) : "r"(addr));
}
__device__ __forceinline__ void mma16816(float* c, const uint* a, const uint* b) {
    asm volatile("mma.sync.aligned.m16n8k16.row.col.f32.bf16.bf16.f32 "
        "{%0,%1,%2,%3},{%4,%5,%6,%7},{%8,%9},{%0,%1,%2,%3};"
        : "+f"(c[0]), "+f"(c[1]), "+f"(c[2]), "+f"(c[3])
        : "r"(a[0]), "r"(a[1]), "r"(a[2]), "r"(a[3]), "r"(b[0]), "r"(b[1]));
}

// ---------------------------------------------------------------------------
// Kernel 1: M = R*E; store M^T hi/lo and sign-folded M^T hi/lo, [j][d].
// ---------------------------------------------------------------------------
__global__ __launch_bounds__(256) void rot_kernel(const float* __restrict__ E,
                                                  const float* __restrict__ theta) {
    __shared__ float sm[8 * 1028];
    const int tid = threadIdx.x;
    const int j0 = blockIdx.x * 8;

    float ct[NQ], st[NQ];
#pragma unroll
    for (int i = 0; i < NQ; i++) sincosf(0.5f * theta[i], &st[i], &ct[i]);

    for (int idx = tid; idx < 8192; idx += 256) {
        int c = idx & 7, d = idx >> 3;
        sm[c * 1028 + d] = E[d * DIM + j0 + c];
    }
    __syncthreads();

    for (int i = 0; i < NQ; i++) {
        const int m = 9 - i;
        for (int t = tid; t < 4096; t += 256) {
            int c = t >> 9, p = t & 511;
            int low = p & ((1 << m) - 1);
            int d0 = ((p >> m) << (m + 1)) | low;
            int d1 = d0 | (1 << m);
            float a0 = sm[c * 1028 + d0];
            float a1 = sm[c * 1028 + d1];
            sm[c * 1028 + d0] = ct[i] * a0 - st[i] * a1;
            sm[c * 1028 + d1] = st[i] * a0 + ct[i] * a1;
        }
        __syncthreads();
    }

    // transposed stores, d fastest -> coalesced
    for (int idx = tid; idx < 8192; idx += 256) {
        int d = idx & 1023, c = idx >> 10;
        float v = sm[c * 1028 + d];
        size_t o = (size_t)(j0 + c) * DIM + d;
        __nv_bfloat16 h = __float2bfloat16(v);
        g_Mth[o] = h;
        g_Mtl[o] = __float2bfloat16(v - __bfloat162float(h));
        float vs = (d < 512) ? v : -v;
        __nv_bfloat16 hs = __float2bfloat16(vs);
        g_Msh[o] = hs;
        g_Msl[o] = __float2bfloat16(vs - __bfloat162float(hs));
    }
}

// ---------------------------------------------------------------------------
// Kernel 2: build A = s-state (bf16 hi/lo) and fp32 copy. One warp per window.
// ---------------------------------------------------------------------------
__global__ __launch_bounds__(128) void state_kernel(const float* __restrict__ x) {
    const int tid = threadIdx.x, lane = tid & 31;
    const int n = blockIdx.x * 4 + (tid >> 5);
    float phi_u = 0.0f, plo_u = 0.0f;
    if (n < NWIN) {
        const int b = n / NWPB;
        const int pos = n - b * NWPB;
        float cs[2][5], sn[2][5];
#pragma unroll
        for (int c = 0; c < 2; c++)
#pragma unroll
            for (int k = 0; k < 5; k++) {
                float v = x[((b * 2 + c) << 12) + pos + k];
                sincosf(0.5f * v, &sn[c][k], &cs[c][k]);
            }
        phi_u = 1.0f; plo_u = 1.0f;
#pragma unroll
        for (int i = 0; i < 5; i++) {
            int bit = (lane >> (4 - i)) & 1;
            phi_u *= bit ? sn[0][i] : cs[0][i];
            plo_u *= bit ? sn[1][i] : cs[1][i];
        }
    }
    __nv_bfloat16* Ah = g_Ah + (size_t)n * DIM;
    __nv_bfloat16* Al = g_Al + (size_t)n * DIM;
    float*         Sf = g_Sf + (size_t)n * DIM;
#pragma unroll 4
    for (int rep = 0; rep < 32; rep++) {
        float ph = __shfl_sync(0xffffffffu, phi_u, rep);
        float s = ph * plo_u;
        __nv_bfloat16 h = __float2bfloat16(s);
        Ah[rep * 32 + lane] = h;
        Al[rep * 32 + lane] = __float2bfloat16(s - __bfloat162float(h));
        Sf[rep * 32 + lane] = s;
    }
}

// ---------------------------------------------------------------------------
// Shared GEMM-stage machinery (R5-proven): stage 64KB = Ah|Al|Bh|Bl blocks of
// [128 rows][128B], 16B-chunk XOR-(row&7) swizzle; Kc=64; 3-stage ring.
// ---------------------------------------------------------------------------
#define STG 65536
#define ZSM_OFF (3 * STG)
#define SMEM_BYTES (3 * STG + 512)

__device__ __forceinline__ void load_stage_raw(uint sb, int buf, int tid,
                                               const __nv_bfloat16* aHp, const __nv_bfloat16* aLp,
                                               const __nv_bfloat16* bHp, const __nv_bfloat16* bLp,
                                               size_t aRow0, size_t bRow0, int kElem) {
    const int row = tid >> 1;
    const int cb = (tid & 1) * 4;
    const int r7 = row & 7;
    const uint dbase = sb + (uint)buf * STG + (uint)row * 128;
    const char* aH = (const char*)(aHp + aRow0 + (size_t)row * DIM + kElem);
    const char* aL = (const char*)(aLp + aRow0 + (size_t)row * DIM + kElem);
    const char* bH = (const char*)(bHp + bRow0 + (size_t)row * DIM + kElem);
    const char* bL = (const char*)(bLp + bRow0 + (size_t)row * DIM + kElem);
#pragma unroll
    for (int cc = 0; cc < 4; cc++) {
        int c = cb + cc;
        uint sw = (uint)((c ^ r7) << 4);
        cpasync16(dbase + sw,         aH + c * 16);
        cpasync16(dbase + 16384 + sw, aL + c * 16);
        cpasync16(dbase + 32768 + sw, bH + c * 16);
        cpasync16(dbase + 49152 + sw, bL + c * 16);
    }
    CP_COMMIT;
}

struct Frag { float acc[64]; };

__device__ __forceinline__ void gemm_stage(uint sb, int buf, int arow0, int ahi,
                                           const int* nrow, int bhi, float* acc) {
    const uint abase = sb + (uint)buf * STG;
    const uint bbase = abase + 32768;
#pragma unroll
    for (int ks = 0; ks < 4; ks++) {
        uint ah[8], al[8], bh[16], bl[16];
#pragma unroll
        for (int i = 0; i < 2; i++) {
            int row = arow0 + 16 * i;
            uint off = (uint)row * 128 + (uint)(((ks * 2 + ahi) ^ (row & 7)) << 4);
            ldsm4(&ah[i * 4], abase + off);
            ldsm4(&al[i * 4], abase + 16384 + off);
        }
#pragma unroll
        for (int jj = 0; jj < 4; jj++) {
            uint off = (uint)nrow[jj] * 128 + (uint)(((ks * 2 + bhi) ^ (nrow[jj] & 7)) << 4);
            ldsm4(&bh[jj * 4], bbase + off);
            ldsm4(&bl[jj * 4], bbase + 16384 + off);
        }
#pragma unroll
        for (int i = 0; i < 2; i++)
#pragma unroll
            for (int j = 0; j < 8; j++) {
                float* c = &acc[(i * 8 + j) * 4];
                mma16816(c, &ah[i * 4], &bh[j * 2]);
                mma16816(c, &ah[i * 4], &bl[j * 2]);
                mma16816(c, &al[i * 4], &bh[j * 2]);
            }
    }
}

// ---------------------------------------------------------------------------
// Kernel 3: Q = M^T Sigma M, lower-triangular tiles, off-diag x2. 36 blocks.
// ---------------------------------------------------------------------------
__global__ __launch_bounds__(256, 1) void qprep_kernel() {
    extern __shared__ __align__(128) char smem[];
    const uint sb = smem_u32(smem);
    const int tid = threadIdx.x, lane = tid & 31, wid = tid >> 5;
    const int warp_m = wid & 3, warp_n = wid >> 2;
    const int r = RT[blockIdx.x], c = CT[blockIdx.x];
    const size_t aRow0 = (size_t)r * 128 * DIM;
    const size_t bRow0 = (size_t)c * 128 * DIM;

    const int arow0 = warp_m * 32 + (lane & 15);
    const int ahi = lane >> 4;
    int nrow[4];
#pragma unroll
    for (int jj = 0; jj < 4; jj++)
        nrow[jj] = warp_n * 64 + jj * 16 + ((lane >> 4) & 1) * 8 + (lane & 7);
    const int bhi = (lane >> 3) & 1;

    float acc[64];
#pragma unroll
    for (int i = 0; i < 64; i++) acc[i] = 0.0f;

    load_stage_raw(sb, 0, tid, g_Mth, g_Mtl, g_Msh, g_Msl, aRow0, bRow0, 0);
    load_stage_raw(sb, 1, tid, g_Mth, g_Mtl, g_Msh, g_Msl, aRow0, bRow0, 64);

    for (int s = 0; s < 16; s++) {
        if (s < 14) CP_WAIT1; else CP_WAIT0;
        __syncthreads();
        if (s + 2 < 16)
            load_stage_raw(sb, (s + 2) % 3, tid, g_Mth, g_Mtl, g_Msh, g_Msl,
                           aRow0, bRow0, (s + 2) * 64);
        gemm_stage(sb, s % 3, arow0, ahi, nrow, bhi, acc);
        __syncthreads();
    }

    const float scale = (r == c) ? 1.0f : 2.0f;
#pragma unroll
    for (int i = 0; i < 2; i++)
#pragma unroll
        for (int j = 0; j < 8; j++) {
            float* cc = &acc[(i * 8 + j) * 4];
            int orow = r * 128 + warp_m * 32 + i * 16 + (lane >> 2);
            int ocol = c * 128 + warp_n * 64 + j * 8 + (lane & 3) * 2;
#pragma unroll
            for (int h = 0; h < 2; h++) {
                int rr = orow + h * 8;
                float q0 = cc[h * 2] * scale, q1 = cc[h * 2 + 1] * scale;
                __nv_bfloat16 h0 = __float2bfloat16(q0);
                __nv_bfloat16 h1 = __float2bfloat16(q1);
                size_t o = (size_t)rr * DIM + ocol;
                g_Qh[o]     = h0;
                g_Qh[o + 1] = h1;
                g_Ql[o]     = __float2bfloat16(q0 - __bfloat162float(h0));
                g_Ql[o + 1] = __float2bfloat16(q1 - __bfloat162float(h1));
            }
        }
}

// ---------------------------------------------------------------------------
// Kernel 4: z_n = sum over 36 lower tiles of s_r^T Q[r,c] s_c (x2 folded in Q).
// Block = 128 windows. 72 stages (2 per tile), weighted epilogue per tile.
// ---------------------------------------------------------------------------
__device__ __forceinline__ void load_stage_main(uint sb, int s, int n0, int tid) {
    const int t = s >> 1, half = s & 1;
    const int r = RT[t], c = CT[t];
    load_stage_raw(sb, s % 3, tid, g_Ah, g_Al, g_Qh, g_Ql,
                   (size_t)n0 * DIM, (size_t)(r * 128) * DIM,
                   c * 128 + half * 64);
}

__global__ __launch_bounds__(256, 1) void qmma_kernel(float* __restrict__ out) {
    extern __shared__ __align__(128) char smem[];
    const uint sb = smem_u32(smem);
    const int tid = threadIdx.x, lane = tid & 31, wid = tid >> 5;
    const int warp_m = wid & 3, warp_n = wid >> 2;
    const int n0 = blockIdx.x * 128;
    float* zsm = (float*)(smem + ZSM_OFF);
    if (tid < 128) zsm[tid] = 0.0f;

    const int arow0 = warp_m * 32 + (lane & 15);
    const int ahi = lane >> 4;
    int nrow[4];
#pragma unroll
    for (int jj = 0; jj < 4; jj++)
        nrow[jj] = warp_n * 64 + jj * 16 + ((lane >> 4) & 1) * 8 + (lane & 7);
    const int bhi = (lane >> 3) & 1;

    float acc[64];
#pragma unroll
    for (int i = 0; i < 64; i++) acc[i] = 0.0f;

    load_stage_main(sb, 0, n0, tid);
    load_stage_main(sb, 1, n0, tid);

    for (int s = 0; s < NSTAGES; s++) {
        if (s < NSTAGES - 2) CP_WAIT1; else CP_WAIT0;
        __syncthreads();
        if (s + 2 < NSTAGES) load_stage_main(sb, s + 2, n0, tid);

        gemm_stage(sb, s % 3, arow0, ahi, nrow, bhi, acc);

        if (s & 1) {                                 // tile complete
            const int r = RT[s >> 1];
            const int colb = r * 128 + warp_n * 64 + (lane & 3) * 2;
#pragma unroll
            for (int i = 0; i < 2; i++) {
                const int rg = warp_m * 32 + i * 16 + (lane >> 2);
                const float* w0p = g_Sf + (size_t)(n0 + rg) * DIM + colb;
                const float* w1p = g_Sf + (size_t)(n0 + rg + 8) * DIM + colb;
                float r0 = 0.0f, r1 = 0.0f;
#pragma unroll
                for (int j = 0; j < 8; j++) {
                    float* cc = &acc[(i * 8 + j) * 4];
                    float2 w0 = __ldg((const float2*)(w0p + j * 8));
                    float2 w1 = __ldg((const float2*)(w1p + j * 8));
                    r0 = fmaf(w0.x, cc[0], fmaf(w0.y, cc[1], r0));
                    r1 = fmaf(w1.x, cc[2], fmaf(w1.y, cc[3], r1));
                }
                r0 += __shfl_xor_sync(0xffffffffu, r0, 1);
                r0 += __shfl_xor_sync(0xffffffffu, r0, 2);
                r1 += __shfl_xor_sync(0xffffffffu, r1, 1);
                r1 += __shfl_xor_sync(0xffffffffu, r1, 2);
                if ((lane & 3) == 0) {
                    atomicAdd(&zsm[rg],     r0);
                    atomicAdd(&zsm[rg + 8], r1);
                }
            }
#pragma unroll
            for (int i = 0; i < 64; i++) acc[i] = 0.0f;
        }
    }

    __syncthreads();
    if (tid < 128) {
        int n = n0 + tid;
        if (n < NWIN) out[n] = zsm[tid];
    }
}

// ---------------------------------------------------------------------------
extern "C" void kernel_launch(void* const* d_in, const int* in_sizes, int n_in,
                              void* d_out, int out_size) {
    const float* x     = (const float*)d_in[0];
    const float* E     = (const float*)d_in[1];
    const float* theta = (const float*)d_in[2];
    float* out = (float*)d_out;

    rot_kernel<<<DIM / 8, 256>>>(E, theta);
    state_kernel<<<NPAD / 4, 128>>>(x);

    cudaFuncSetAttribute(qprep_kernel,
                         cudaFuncAttributeMaxDynamicSharedMemorySize, SMEM_BYTES);
    qprep_kernel<<<NTILES, 256, SMEM_BYTES>>>();

    cudaFuncSetAttribute(qmma_kernel,
                         cudaFuncAttributeMaxDynamicSharedMemorySize, SMEM_BYTES);
    qmma_kernel<<<NPAD / 128, 256, SMEM_BYTES>>>(out);
}

// round 9
// speedup vs baseline: 2.0254x; 1.2417x over previous
#include <cuda_runtime.h>
#include <cuda_bf16.h>
#include <cstdint>

#define DIM   1024
#define NQ    10
#define NWIN  65472
#define NWPB  4092
#define NPAD  65536
#define NTILES  36

typedef unsigned long long ull;
typedef unsigned int uint;

// M^T hi/lo [j][d], and sign-folded M^T for Q = M^T Sigma M (bf16, qprep only)
__device__ __nv_bfloat16 g_Mth[DIM * DIM];
__device__ __nv_bfloat16 g_Mtl[DIM * DIM];
__device__ __nv_bfloat16 g_Msh[DIM * DIM];
__device__ __nv_bfloat16 g_Msl[DIM * DIM];
// folded Q int8 limbs (lower tiles, off-diag x2): F ~= (Qa + Qb/256)/127
__device__ char g_Qa[DIM * DIM];
__device__ char g_Qb[DIM * DIM];
// s-state int8 limbs: s ~= (Aa + Ab/256)/127 ; plus fp32 copy for epilogue
__device__ char  g_Aa[(size_t)NPAD * DIM];
__device__ char  g_Ab[(size_t)NPAD * DIM];
__device__ float g_Sf[(size_t)NPAD * DIM];

__device__ const unsigned char RT[NTILES] =
    {0,1,1,2,2,2,3,3,3,3,4,4,4,4,4,5,5,5,5,5,5,6,6,6,6,6,6,6,7,7,7,7,7,7,7,7};
__device__ const unsigned char CT[NTILES] =
    {0,0,1,0,1,2,0,1,2,3,0,1,2,3,4,0,1,2,3,4,5,0,1,2,3,4,5,6,0,1,2,3,4,5,6,7};

static __device__ __forceinline__ uint smem_u32(const void* p) {
    return (uint)__cvta_generic_to_shared(p);
}
__device__ __forceinline__ void cpasync16(uint dst, const void* src) {
    asm volatile("cp.async.cg.shared.global [%0], [%1], 16;" :: "r"(dst), "l"(src) : "memory");
}
#define CP_COMMIT asm volatile("cp.async.commit_group;" ::: "memory")
#define CP_WAIT1  asm volatile("cp.async.wait_group 1;" ::: "memory")
#define CP_WAIT0  asm volatile("cp.async.wait_group 0;" ::: "memory")

__device__ __forceinline__ void ldsm4(uint* r, uint addr) {
    asm volatile("ldmatrix.sync.aligned.m8n8.x4.shared.b16 {%0,%1,%2,%3}, [%4];"
                 : "=r"(r[0]), "=r"(r[1]), "=r"(r[2]), "=r"(r[3]) : "r"(addr));
}
__device__ __forceinline__ void mma16816(float* c, const uint* a, const uint* b) {
    asm volatile("mma.sync.aligned.m16n8k16.row.col.f32.bf16.bf16.f32 "
        "{%0,%1,%2,%3},{%4,%5,%6,%7},{%8,%9},{%0,%1,%2,%3};"
        : "+f"(c[0]), "+f"(c[1]), "+f"(c[2]), "+f"(c[3])
        : "r"(a[0]), "r"(a[1]), "r"(a[2]), "r"(a[3]), "r"(b[0]), "r"(b[1]));
}
__device__ __forceinline__ void mma16832s8(int* c, const uint* a, const uint* b) {
    asm volatile("mma.sync.aligned.m16n8k32.row.col.s32.s8.s8.s32 "
        "{%0,%1,%2,%3},{%4,%5,%6,%7},{%8,%9},{%0,%1,%2,%3};"
        : "+r"(c[0]), "+r"(c[1]), "+r"(c[2]), "+r"(c[3])
        : "r"(a[0]), "r"(a[1]), "r"(a[2]), "r"(a[3]), "r"(b[0]), "r"(b[1]));
}
__device__ __forceinline__ float clamp127(float v) {
    return fminf(fmaxf(v, -127.0f), 127.0f);
}

// ---------------------------------------------------------------------------
// Kernel 1: M = R*E; store M^T hi/lo and sign-folded M^T hi/lo, [j][d].
// ---------------------------------------------------------------------------
__global__ __launch_bounds__(256) void rot_kernel(const float* __restrict__ E,
                                                  const float* __restrict__ theta) {
    __shared__ float sm[8 * 1028];
    const int tid = threadIdx.x;
    const int j0 = blockIdx.x * 8;

    float ct[NQ], st[NQ];
#pragma unroll
    for (int i = 0; i < NQ; i++) sincosf(0.5f * theta[i], &st[i], &ct[i]);

    for (int idx = tid; idx < 8192; idx += 256) {
        int c = idx & 7, d = idx >> 3;
        sm[c * 1028 + d] = E[d * DIM + j0 + c];
    }
    __syncthreads();

    for (int i = 0; i < NQ; i++) {
        const int m = 9 - i;
        for (int t = tid; t < 4096; t += 256) {
            int c = t >> 9, p = t & 511;
            int low = p & ((1 << m) - 1);
            int d0 = ((p >> m) << (m + 1)) | low;
            int d1 = d0 | (1 << m);
            float a0 = sm[c * 1028 + d0];
            float a1 = sm[c * 1028 + d1];
            sm[c * 1028 + d0] = ct[i] * a0 - st[i] * a1;
            sm[c * 1028 + d1] = st[i] * a0 + ct[i] * a1;
        }
        __syncthreads();
    }

    for (int idx = tid; idx < 8192; idx += 256) {
        int d = idx & 1023, c = idx >> 10;
        float v = sm[c * 1028 + d];
        size_t o = (size_t)(j0 + c) * DIM + d;
        __nv_bfloat16 h = __float2bfloat16(v);
        g_Mth[o] = h;
        g_Mtl[o] = __float2bfloat16(v - __bfloat162float(h));
        float vs = (d < 512) ? v : -v;
        __nv_bfloat16 hs = __float2bfloat16(vs);
        g_Msh[o] = hs;
        g_Msl[o] = __float2bfloat16(vs - __bfloat162float(hs));
    }
}

// ---------------------------------------------------------------------------
// Kernel 2: s-state int8 limbs (radix 256, scale 127) + fp32 copy.
// ---------------------------------------------------------------------------
__global__ __launch_bounds__(128) void state_kernel(const float* __restrict__ x) {
    const int tid = threadIdx.x, lane = tid & 31;
    const int n = blockIdx.x * 4 + (tid >> 5);
    float phi_u = 0.0f, plo_u = 0.0f;
    if (n < NWIN) {
        const int b = n / NWPB;
        const int pos = n - b * NWPB;
        float cs[2][5], sn[2][5];
#pragma unroll
        for (int c = 0; c < 2; c++)
#pragma unroll
            for (int k = 0; k < 5; k++) {
                float v = x[((b * 2 + c) << 12) + pos + k];
                sincosf(0.5f * v, &sn[c][k], &cs[c][k]);
            }
        phi_u = 1.0f; plo_u = 1.0f;
#pragma unroll
        for (int i = 0; i < 5; i++) {
            int bit = (lane >> (4 - i)) & 1;
            phi_u *= bit ? sn[0][i] : cs[0][i];
            plo_u *= bit ? sn[1][i] : cs[1][i];
        }
    }
    char*  Aa = g_Aa + (size_t)n * DIM;
    char*  Ab = g_Ab + (size_t)n * DIM;
    float* Sf = g_Sf + (size_t)n * DIM;
#pragma unroll 4
    for (int rep = 0; rep < 32; rep++) {
        float ph = __shfl_sync(0xffffffffu, phi_u, rep);
        float s = ph * plo_u;
        float s127 = s * 127.0f;
        float a1 = clamp127(rintf(s127));
        float a2 = clamp127(rintf((s127 - a1) * 256.0f));
        Aa[rep * 32 + lane] = (char)(int)a1;
        Ab[rep * 32 + lane] = (char)(int)a2;
        Sf[rep * 32 + lane] = s;
    }
}

// ---------------------------------------------------------------------------
// bf16 GEMM-stage machinery (R5/R7-proven) for qprep only.
// ---------------------------------------------------------------------------
#define STG 65536
#define ZSM_OFF (3 * STG)
#define SMEM_BYTES (3 * STG + 512)

__device__ __forceinline__ void load_stage_bf16(uint sb, int buf, int tid,
                                                const __nv_bfloat16* aHp, const __nv_bfloat16* aLp,
                                                const __nv_bfloat16* bHp, const __nv_bfloat16* bLp,
                                                size_t aRow0, size_t bRow0, int kElem) {
    const int row = tid >> 1;
    const int cb = (tid & 1) * 4;
    const int r7 = row & 7;
    const uint dbase = sb + (uint)buf * STG + (uint)row * 128;
    const char* aH = (const char*)(aHp + aRow0 + (size_t)row * DIM + kElem);
    const char* aL = (const char*)(aLp + aRow0 + (size_t)row * DIM + kElem);
    const char* bH = (const char*)(bHp + bRow0 + (size_t)row * DIM + kElem);
    const char* bL = (const char*)(bLp + bRow0 + (size_t)row * DIM + kElem);
#pragma unroll
    for (int cc = 0; cc < 4; cc++) {
        int c = cb + cc;
        uint sw = (uint)((c ^ r7) << 4);
        cpasync16(dbase + sw,         aH + c * 16);
        cpasync16(dbase + 16384 + sw, aL + c * 16);
        cpasync16(dbase + 32768 + sw, bH + c * 16);
        cpasync16(dbase + 49152 + sw, bL + c * 16);
    }
    CP_COMMIT;
}

__device__ __forceinline__ void gemm_stage_bf16(uint sb, int buf, int arow0, int ahi,
                                                const int* nrow, int bhi, float* acc) {
    const uint abase = sb + (uint)buf * STG;
    const uint bbase = abase + 32768;
#pragma unroll
    for (int ks = 0; ks < 4; ks++) {
        uint ah[8], al[8], bh[16], bl[16];
#pragma unroll
        for (int i = 0; i < 2; i++) {
            int row = arow0 + 16 * i;
            uint off = (uint)row * 128 + (uint)(((ks * 2 + ahi) ^ (row & 7)) << 4);
            ldsm4(&ah[i * 4], abase + off);
            ldsm4(&al[i * 4], abase + 16384 + off);
        }
#pragma unroll
        for (int jj = 0; jj < 4; jj++) {
            uint off = (uint)nrow[jj] * 128 + (uint)(((ks * 2 + bhi) ^ (nrow[jj] & 7)) << 4);
            ldsm4(&bh[jj * 4], bbase + off);
            ldsm4(&bl[jj * 4], bbase + 16384 + off);
        }
#pragma unroll
        for (int i = 0; i < 2; i++)
#pragma unroll
            for (int j = 0; j < 8; j++) {
                float* c = &acc[(i * 8 + j) * 4];
                mma16816(c, &ah[i * 4], &bh[j * 2]);
                mma16816(c, &ah[i * 4], &bl[j * 2]);
                mma16816(c, &al[i * 4], &bh[j * 2]);
            }
    }
}

// ---------------------------------------------------------------------------
// Kernel 3: Q = M^T Sigma M -> folded int8 limbs (radix 256, scale 127).
// ---------------------------------------------------------------------------
__global__ __launch_bounds__(256, 1) void qprep_kernel() {
    extern __shared__ __align__(128) char smem[];
    const uint sb = smem_u32(smem);
    const int tid = threadIdx.x, lane = tid & 31, wid = tid >> 5;
    const int warp_m = wid & 3, warp_n = wid >> 2;
    const int r = RT[blockIdx.x], c = CT[blockIdx.x];
    const size_t aRow0 = (size_t)r * 128 * DIM;
    const size_t bRow0 = (size_t)c * 128 * DIM;

    const int arow0 = warp_m * 32 + (lane & 15);
    const int ahi = lane >> 4;
    int nrow[4];
#pragma unroll
    for (int jj = 0; jj < 4; jj++)
        nrow[jj] = warp_n * 64 + jj * 16 + ((lane >> 4) & 1) * 8 + (lane & 7);
    const int bhi = (lane >> 3) & 1;

    float acc[64];
#pragma unroll
    for (int i = 0; i < 64; i++) acc[i] = 0.0f;

    load_stage_bf16(sb, 0, tid, g_Mth, g_Mtl, g_Msh, g_Msl, aRow0, bRow0, 0);
    load_stage_bf16(sb, 1, tid, g_Mth, g_Mtl, g_Msh, g_Msl, aRow0, bRow0, 64);

    for (int s = 0; s < 16; s++) {
        if (s < 14) CP_WAIT1; else CP_WAIT0;
        __syncthreads();
        if (s + 2 < 16)
            load_stage_bf16(sb, (s + 2) % 3, tid, g_Mth, g_Mtl, g_Msh, g_Msl,
                            aRow0, bRow0, (s + 2) * 64);
        gemm_stage_bf16(sb, s % 3, arow0, ahi, nrow, bhi, acc);
        __syncthreads();
    }

    const float scale = (r == c) ? 1.0f : 2.0f;
#pragma unroll
    for (int i = 0; i < 2; i++)
#pragma unroll
        for (int j = 0; j < 8; j++) {
            float* cc = &acc[(i * 8 + j) * 4];
            int orow = r * 128 + warp_m * 32 + i * 16 + (lane >> 2);
            int ocol = c * 128 + warp_n * 64 + j * 8 + (lane & 3) * 2;
#pragma unroll
            for (int h = 0; h < 2; h++) {
                int rr = orow + h * 8;
#pragma unroll
                for (int e = 0; e < 2; e++) {
                    float q127 = cc[h * 2 + e] * scale * 127.0f;
                    float b1 = clamp127(rintf(q127));
                    float b2 = clamp127(rintf((q127 - b1) * 256.0f));
                    size_t o = (size_t)rr * DIM + ocol + e;
                    g_Qa[o] = (char)(int)b1;
                    g_Qb[o] = (char)(int)b2;
                }
            }
        }
}

// ---------------------------------------------------------------------------
// Kernel 4: exact 4-pass int8 limb GEMM. Block = 128 windows, 36 tile-stages.
// Stage (64KB): A1|A2|B1|B2 regions [128 rows][128B], XOR-(row&7) swizzle.
// t = (I11 + Imid/256 + I22/65536)/127^2 ; zp += w*t ; reduce once at end.
// ---------------------------------------------------------------------------
__device__ __forceinline__ void load_stage_s8(uint sb, int s, int n0, int tid) {
    const int r = RT[s], c = CT[s];
    const int row = tid >> 1;
    const int cb = (tid & 1) * 4;
    const int r7 = row & 7;
    const uint dbase = sb + (uint)(s % 3) * STG + (uint)row * 128;
    const char* a1 = g_Aa + (size_t)(n0 + row) * DIM + c * 128;
    const char* a2 = g_Ab + (size_t)(n0 + row) * DIM + c * 128;
    const char* b1 = g_Qa + (size_t)(r * 128 + row) * DIM + c * 128;
    const char* b2 = g_Qb + (size_t)(r * 128 + row) * DIM + c * 128;
#pragma unroll
    for (int cc = 0; cc < 4; cc++) {
        int ch = cb + cc;
        uint sw = (uint)((ch ^ r7) << 4);
        cpasync16(dbase + sw,         a1 + ch * 16);
        cpasync16(dbase + 16384 + sw, a2 + ch * 16);
        cpasync16(dbase + 32768 + sw, b1 + ch * 16);
        cpasync16(dbase + 49152 + sw, b2 + ch * 16);
    }
    CP_COMMIT;
}

__global__ __launch_bounds__(256, 1) void qmma_kernel(float* __restrict__ out) {
    extern __shared__ __align__(128) char smem[];
    const uint sb = smem_u32(smem);
    const int tid = threadIdx.x, lane = tid & 31, wid = tid >> 5;
    const int warp_m = wid & 3, warp_n = wid >> 2;
    const int n0 = blockIdx.x * 128;
    float* zsm = (float*)(smem + ZSM_OFF);
    if (tid < 128) zsm[tid] = 0.0f;

    const int arow0 = warp_m * 32 + (lane & 15);
    const int ahi = lane >> 4;
    int nrow[4];
#pragma unroll
    for (int jj = 0; jj < 4; jj++)
        nrow[jj] = warp_n * 64 + jj * 16 + ((lane >> 4) & 1) * 8 + (lane & 7);
    const int bhi = (lane >> 3) & 1;

    const float k1 = 1.0f / 16129.0f;
    const float k2 = k1 / 256.0f;
    const float k3 = k1 / 65536.0f;

    int i11[64], imd[64];
    float zp[4] = {0.0f, 0.0f, 0.0f, 0.0f};
#pragma unroll
    for (int i = 0; i < 64; i++) { i11[i] = 0; imd[i] = 0; }

    load_stage_s8(sb, 0, n0, tid);
    load_stage_s8(sb, 1, n0, tid);

    for (int s = 0; s < NTILES; s++) {
        if (s < NTILES - 2) CP_WAIT1; else CP_WAIT0;
        __syncthreads();
        if (s + 2 < NTILES) load_stage_s8(sb, s + 2, n0, tid);

        const uint A1 = sb + (uint)(s % 3) * STG;
        const uint A2 = A1 + 16384, B1 = A1 + 32768, B2 = A1 + 49152;

        // ---- pass 1&2: a1b1 -> i11 ; a1b2 + a2b1 -> imd -------------------
#pragma unroll
        for (int ks = 0; ks < 4; ks++) {
            uint a1f[8], a2f[8];
#pragma unroll
            for (int i = 0; i < 2; i++) {
                int row = arow0 + 16 * i;
                uint off = (uint)row * 128 + (uint)(((ks * 2 + ahi) ^ (row & 7)) << 4);
                ldsm4(&a1f[i * 4], A1 + off);
                ldsm4(&a2f[i * 4], A2 + off);
            }
#pragma unroll
            for (int jj = 0; jj < 4; jj++) {
                uint b1f[4], b2f[4];
                uint off = (uint)nrow[jj] * 128 + (uint)(((ks * 2 + bhi) ^ (nrow[jj] & 7)) << 4);
                ldsm4(b1f, B1 + off);
                ldsm4(b2f, B2 + off);
#pragma unroll
                for (int i = 0; i < 2; i++)
#pragma unroll
                    for (int jh = 0; jh < 2; jh++) {
                        int idx = (i * 8 + jj * 2 + jh) * 4;
                        mma16832s8(&i11[idx], &a1f[i * 4], &b1f[jh * 2]);
                        mma16832s8(&imd[idx], &a1f[i * 4], &b2f[jh * 2]);
                        mma16832s8(&imd[idx], &a2f[i * 4], &b1f[jh * 2]);
                    }
            }
        }

        // ---- drain A: zp += w*(i11*k1 + imd*k2) ; reset -------------------
        const int rt = RT[s];
        const int colb = rt * 128 + warp_n * 64 + (lane & 3) * 2;
#pragma unroll
        for (int i = 0; i < 2; i++) {
            const int rg = warp_m * 32 + i * 16 + (lane >> 2);
            const float* w0p = g_Sf + (size_t)(n0 + rg) * DIM + colb;
            const float* w1p = g_Sf + (size_t)(n0 + rg + 8) * DIM + colb;
#pragma unroll
            for (int j = 0; j < 8; j++) {
                int idx = (i * 8 + j) * 4;
                float2 w0 = __ldg((const float2*)(w0p + j * 8));
                float2 w1 = __ldg((const float2*)(w1p + j * 8));
                float t0 = fmaf((float)imd[idx + 0], k2, (float)i11[idx + 0] * k1);
                float t1 = fmaf((float)imd[idx + 1], k2, (float)i11[idx + 1] * k1);
                float t2 = fmaf((float)imd[idx + 2], k2, (float)i11[idx + 2] * k1);
                float t3 = fmaf((float)imd[idx + 3], k2, (float)i11[idx + 3] * k1);
                zp[i * 2]     = fmaf(w0.x, t0, fmaf(w0.y, t1, zp[i * 2]));
                zp[i * 2 + 1] = fmaf(w1.x, t2, fmaf(w1.y, t3, zp[i * 2 + 1]));
                i11[idx + 0] = 0; i11[idx + 1] = 0; i11[idx + 2] = 0; i11[idx + 3] = 0;
                imd[idx + 0] = 0; imd[idx + 1] = 0; imd[idx + 2] = 0; imd[idx + 3] = 0;
            }
        }

        // ---- pass 3: a2b2 -> i11 (reused) ---------------------------------
#pragma unroll
        for (int ks = 0; ks < 4; ks++) {
            uint a2f[8];
#pragma unroll
            for (int i = 0; i < 2; i++) {
                int row = arow0 + 16 * i;
                uint off = (uint)row * 128 + (uint)(((ks * 2 + ahi) ^ (row & 7)) << 4);
                ldsm4(&a2f[i * 4], A2 + off);
            }
#pragma unroll
            for (int jj = 0; jj < 4; jj++) {
                uint b2f[4];
                uint off = (uint)nrow[jj] * 128 + (uint)(((ks * 2 + bhi) ^ (nrow[jj] & 7)) << 4);
                ldsm4(b2f, B2 + off);
#pragma unroll
                for (int i = 0; i < 2; i++)
#pragma unroll
                    for (int jh = 0; jh < 2; jh++)
                        mma16832s8(&i11[(i * 8 + jj * 2 + jh) * 4], &a2f[i * 4], &b2f[jh * 2]);
            }
        }

        // ---- drain B: zp += w*(i11*k3) ; reset ----------------------------
#pragma unroll
        for (int i = 0; i < 2; i++) {
            const int rg = warp_m * 32 + i * 16 + (lane >> 2);
            const float* w0p = g_Sf + (size_t)(n0 + rg) * DIM + colb;
            const float* w1p = g_Sf + (size_t)(n0 + rg + 8) * DIM + colb;
#pragma unroll
            for (int j = 0; j < 8; j++) {
                int idx = (i * 8 + j) * 4;
                float2 w0 = __ldg((const float2*)(w0p + j * 8));
                float2 w1 = __ldg((const float2*)(w1p + j * 8));
                zp[i * 2]     = fmaf(w0.x, (float)i11[idx + 0] * k3,
                                fmaf(w0.y, (float)i11[idx + 1] * k3, zp[i * 2]));
                zp[i * 2 + 1] = fmaf(w1.x, (float)i11[idx + 2] * k3,
                                fmaf(w1.y, (float)i11[idx + 3] * k3, zp[i * 2 + 1]));
                i11[idx + 0] = 0; i11[idx + 1] = 0; i11[idx + 2] = 0; i11[idx + 3] = 0;
            }
        }
    }

    // ---- final reduction (once) ------------------------------------------
#pragma unroll
    for (int q = 0; q < 4; q++) {
        zp[q] += __shfl_xor_sync(0xffffffffu, zp[q], 1);
        zp[q] += __shfl_xor_sync(0xffffffffu, zp[q], 2);
    }
    if ((lane & 3) == 0) {
        const int rbase = warp_m * 32 + (lane >> 2);
        atomicAdd(&zsm[rbase],      zp[0]);
        atomicAdd(&zsm[rbase + 8],  zp[1]);
        atomicAdd(&zsm[rbase + 16], zp[2]);
        atomicAdd(&zsm[rbase + 24], zp[3]);
    }

    __syncthreads();
    if (tid < 128) {
        int n = n0 + tid;
        if (n < NWIN) out[n] = zsm[tid];
    }
}

// ---------------------------------------------------------------------------
extern "C" void kernel_launch(void* const* d_in, const int* in_sizes, int n_in,
                              void* d_out, int out_size) {
    const float* x     = (const float*)d_in[0];
    const float* E     = (const float*)d_in[1];
    const float* theta = (const float*)d_in[2];
    float* out = (float*)d_out;

    rot_kernel<<<DIM / 8, 256>>>(E, theta);
    state_kernel<<<NPAD / 4, 128>>>(x);

    cudaFuncSetAttribute(qprep_kernel,
                         cudaFuncAttributeMaxDynamicSharedMemorySize, SMEM_BYTES);
    qprep_kernel<<<NTILES, 256, SMEM_BYTES>>>();

    cudaFuncSetAttribute(qmma_kernel,
                         cudaFuncAttributeMaxDynamicSharedMemorySize, SMEM_BYTES);
    qmma_kernel<<<NPAD / 128, 256, SMEM_BYTES>>>(out);
}